// round 1
// baseline (speedup 1.0000x reference)
#include <cuda_runtime.h>
#include <cstdint>

#define BATCH 512
#define NCTX  1000
#define DCTX  128
#define NH    8
#define HID   128
#define TN    128      // tile rows
#define NTILES 8       // ceil(1000/128)
#define TPB   1024
#define ROWP  132      // padded row stride in floats (bank-conflict-free)

// ---- smem layout (float offsets) ----
#define OFF_CTX0   0
#define OFF_CTX1   16896                  // 128*132
#define OFF_QK     33792                  // 8*132
#define OFF_E      34848                  // 8*132
#define OFF_COMP   35904                  // 8*132
#define OFF_C      36960                  // 8*128
#define OFF_X      37984                  // 128
#define OFF_XF     38112                  // 128
#define OFF_Z      38240                  // 128
#define OFF_STATE  38368                  // 384
#define OFF_Q      38752                  // 128
#define OFF_U      38880                  // 1024
#define OFF_MASK   39904                  // 2*128 ints
#define OFF_RED    40160                  // 80 floats of reduction state
#define SMEM_FLOATS 40240
#define SMEM_BYTES  (SMEM_FLOATS * 4)

// sred indices
#define R_MRUN  0
#define R_LRUN  8
#define R_MNEW  16
#define R_SCALE 24
#define R_WARP  32
#define R_UMAX  64
#define R_USUM  65

typedef unsigned long long ull;

__device__ __forceinline__ ull f2pack(float lo, float hi) {
    ull r; asm("mov.b64 %0, {%1,%2};" : "=l"(r) : "f"(lo), "f"(hi)); return r;
}
__device__ __forceinline__ void f2unpack(ull v, float &lo, float &hi) {
    asm("mov.b64 {%0,%1}, %2;" : "=f"(lo), "=f"(hi) : "l"(v));
}
__device__ __forceinline__ ull ffma2(ull a, ull b, ull c) {
    ull d; asm("fma.rn.f32x2 %0, %1, %2, %3;" : "=l"(d) : "l"(a), "l"(b), "l"(c)); return d;
}
__device__ __forceinline__ ull fmul2(ull a, ull b) {
    ull d; asm("mul.rn.f32x2 %0, %1, %2;" : "=l"(d) : "l"(a), "l"(b)); return d;
}

__device__ __forceinline__ void cpasync16(uint32_t dst, const void* src, int srcbytes) {
    asm volatile("cp.async.cg.shared.global [%0], [%1], 16, %2;"
                 :: "r"(dst), "l"(src), "r"(srcbytes));
}
__device__ __forceinline__ void cp_commit() { asm volatile("cp.async.commit_group;"); }
template <int NG> __device__ __forceinline__ void cp_wait() {
    asm volatile("cp.async.wait_group %0;" :: "n"(NG));
}

__device__ __forceinline__ void issue_tile(int tile, int b, const float* __restrict__ context,
                                           const int* __restrict__ mask,
                                           float* S, int t) {
    const int bufi = tile & 1;
    float* dctx = S + (bufi ? OFF_CTX1 : OFF_CTX0);
    int*   dmask = (int*)(S + OFF_MASK) + bufi * 128;
    const int n0 = tile * TN;
#pragma unroll
    for (int k = 0; k < 4; ++k) {
        int idx = t + k * TPB;              // 0..4095
        int row = idx >> 5, c4 = idx & 31;  // 32 float4 per row
        const float* src = context + ((size_t)b * NCTX + (size_t)(n0 + row)) * DCTX + c4 * 4;
        uint32_t dst = (uint32_t)__cvta_generic_to_shared(dctx + row * ROWP + c4 * 4);
        int ok = (n0 + row < NCTX) ? 16 : 0;   // zero-fill OOB rows
        cpasync16(dst, src, ok);
    }
    if (t < 32) {
        const int* srcm = mask + (size_t)b * NCTX + n0 + t * 4;
        uint32_t dst = (uint32_t)__cvta_generic_to_shared(dmask + t * 4);
        int ok = (n0 + t * 4 < NCTX) ? 16 : 0;  // NCTX multiple of 4
        cpasync16(dst, srcm, ok);
    }
    cp_commit();
}

extern __shared__ float S[];

__global__ void __launch_bounds__(TPB, 1)
pointer_attn_kernel(const float* __restrict__ state_t,
                    const float* __restrict__ context,
                    const int*   __restrict__ mask,
                    const float* __restrict__ Wq,
                    const float* __restrict__ Wk_mha,
                    const float* __restrict__ Wv,
                    const float* __restrict__ Wfc,
                    const float* __restrict__ Wk,
                    const int*   __restrict__ Tptr,
                    float*       __restrict__ out)
{
    const int b = blockIdx.x;
    const int t = threadIdx.x;
    const float NEG_INF = __int_as_float(0xff800000u);

    float* sqk   = S + OFF_QK;
    float* se    = S + OFF_E;
    float* scomp = S + OFF_COMP;
    float* sc    = S + OFF_C;
    float* sx    = S + OFF_X;
    float* sxf   = S + OFF_XF;
    float* sz    = S + OFF_Z;
    float* sstate= S + OFF_STATE;
    float* sq    = S + OFF_Q;
    float* su    = S + OFF_U;
    float* sred  = S + OFF_RED;

    // kick off tile 0 load ASAP (hides DRAM latency behind the q projection)
    issue_tile(0, b, context, mask, S, t);

    // ---- prologue: load state, init ----
    if (t < 384) sstate[t] = state_t[(size_t)b * 384 + t];
    if (t < 8) { sred[R_MRUN + t] = NEG_INF; sred[R_LRUN + t] = 0.f; }
    su[t] = NEG_INF;
    __syncthreads();

    // q[o] = sum_i state[i] * Wq[i,o]   (split-K by 8)
    {
        int o = t >> 3, ks = t & 7;
        float p = 0.f;
#pragma unroll
        for (int j = 0; j < 48; ++j) {
            int i = ks * 48 + j;
            p = fmaf(sstate[i], Wq[i * HID + o], p);
        }
        p += __shfl_xor_sync(0xffffffffu, p, 4);
        p += __shfl_xor_sync(0xffffffffu, p, 2);
        p += __shfl_xor_sync(0xffffffffu, p, 1);
        if (ks == 0) sq[o] = p;
    }
    __syncthreads();

    // qk[h][d] = 0.25 * sum_j Wk_mha[d, 16h+j] * q[16h+j]
    {
        int d = t >> 3, h = t & 7;
        float p = 0.f;
#pragma unroll
        for (int j = 0; j < 16; ++j)
            p = fmaf(Wk_mha[d * HID + h * 16 + j], sq[h * 16 + j], p);
        sqk[h * ROWP + d] = 0.25f * p;
    }

    issue_tile(1, b, context, mask, S, t);  // pipeline depth 2
    __syncthreads();

    // ---- pass 1: flash-style online softmax + weighted-context accumulation ----
    ull acc[NH][2];
#pragma unroll
    for (int hh = 0; hh < NH; ++hh) { acc[hh][0] = 0ull; acc[hh][1] = 0ull; }

    const int nA = t >> 3, hA = t & 7;    // comp-phase role
    const int wI = t >> 5, lane = t & 31; // acc-phase role

    for (int tile = 0; tile < NTILES; ++tile) {
        const float* C = S + ((tile & 1) ? OFF_CTX1 : OFF_CTX0);
        const int*   M = (const int*)(S + OFF_MASK) + (tile & 1) * 128;

        if (tile + 2 < NTILES) { cp_wait<1>(); }
        else                   { cp_wait<0>(); }
        __syncthreads();

        // Phase A: comp[n][h] = ctx[n] . qk[h]
        float comp;
        bool dead;
        {
            const float4* cr = (const float4*)(C + nA * ROWP);
            const float4* qr = (const float4*)(sqk + hA * ROWP);
            ull a0 = 0ull, a1 = 0ull;
#pragma unroll
            for (int i = 0; i < 32; i += 2) {
                float4 x0 = cr[i],   q0 = qr[i];
                float4 x1 = cr[i+1], q1 = qr[i+1];
                a0 = ffma2(f2pack(x0.x, x0.y), f2pack(q0.x, q0.y), a0);
                a1 = ffma2(f2pack(x0.z, x0.w), f2pack(q0.z, q0.w), a1);
                a0 = ffma2(f2pack(x1.x, x1.y), f2pack(q1.x, q1.y), a0);
                a1 = ffma2(f2pack(x1.z, x1.w), f2pack(q1.z, q1.w), a1);
            }
            float p0, p1, p2, p3;
            f2unpack(a0, p0, p1); f2unpack(a1, p2, p3);
            comp = (p0 + p1) + (p2 + p3);
            int gn = tile * TN + nA;
            dead = (gn >= NCTX) || (M[nA] != 0);
            if (dead) comp = NEG_INF;
            scomp[hA * ROWP + nA] = comp;
        }
        __syncthreads();

        // tile max per head + merge with running max
        if (t < 256) {
            int w = t >> 5, l = t & 31;
            float v = fmaxf(fmaxf(scomp[w * ROWP + l],      scomp[w * ROWP + l + 32]),
                            fmaxf(scomp[w * ROWP + l + 64], scomp[w * ROWP + l + 96]));
            v = fmaxf(v, __shfl_xor_sync(0xffffffffu, v, 16));
            v = fmaxf(v, __shfl_xor_sync(0xffffffffu, v, 8));
            v = fmaxf(v, __shfl_xor_sync(0xffffffffu, v, 4));
            v = fmaxf(v, __shfl_xor_sync(0xffffffffu, v, 2));
            v = fmaxf(v, __shfl_xor_sync(0xffffffffu, v, 1));
            if (l == 0) {
                float mo = sred[R_MRUN + w];
                float mn = fmaxf(mo, v);
                float scl = (mo == mn) ? 1.f : __expf(mo - mn);
                sred[R_MNEW + w]  = mn;
                sred[R_SCALE + w] = scl;
                sred[R_MRUN + w]  = mn;
                sred[R_LRUN + w] *= scl;
            }
        }
        __syncthreads();

        // Phase B: e = exp(comp - m_new)
        {
            float mn = sred[R_MNEW + hA];
            float e = dead ? 0.f : __expf(comp - mn);
            se[hA * ROWP + nA] = e;
        }
        __syncthreads();

        // l accumulation (warps 0..7), then everyone does acc
        if (t < 256) {
            int w = t >> 5, l = t & 31;
            float v = se[w * ROWP + l] + se[w * ROWP + l + 32]
                    + se[w * ROWP + l + 64] + se[w * ROWP + l + 96];
            v += __shfl_xor_sync(0xffffffffu, v, 16);
            v += __shfl_xor_sync(0xffffffffu, v, 8);
            v += __shfl_xor_sync(0xffffffffu, v, 4);
            v += __shfl_xor_sync(0xffffffffu, v, 2);
            v += __shfl_xor_sync(0xffffffffu, v, 1);
            if (l == 0) sred[R_LRUN + w] += v;
        }

        // acc: c_h += e[h][n] * ctx[n][:]  — warp owns 4 rows, lane owns 4 cols, all 8 heads
        {
#pragma unroll
            for (int hh = 0; hh < NH; ++hh) {
                float scl = sred[R_SCALE + hh];
                ull s2 = f2pack(scl, scl);
                acc[hh][0] = fmul2(acc[hh][0], s2);
                acc[hh][1] = fmul2(acc[hh][1], s2);
            }
#pragma unroll
            for (int r = 0; r < 4; ++r) {
                int nn = wI * 4 + r;
                float4 cv = *(const float4*)(C + nn * ROWP + lane * 4);
                ull c01 = f2pack(cv.x, cv.y), c23 = f2pack(cv.z, cv.w);
#pragma unroll
                for (int hh = 0; hh < NH; ++hh) {
                    float e = se[hh * ROWP + nn];
                    ull e2 = f2pack(e, e);
                    acc[hh][0] = ffma2(c01, e2, acc[hh][0]);
                    acc[hh][1] = ffma2(c23, e2, acc[hh][1]);
                }
            }
        }
        __syncthreads();  // protect buffer before next issue

        if (tile + 2 < NTILES) issue_tile(tile + 2, b, context, mask, S, t);
    }

    // ---- reduce per-warp partials into c[h][d] (reuse ctx buffers as scratch) ----
    {
        float* base = S + OFF_CTX0 + wI * (NH * DCTX);
#pragma unroll
        for (int hh = 0; hh < NH; ++hh) {
            float x0, x1, x2, x3;
            f2unpack(acc[hh][0], x0, x1);
            f2unpack(acc[hh][1], x2, x3);
            *(float4*)(base + hh * DCTX + lane * 4) = make_float4(x0, x1, x2, x3);
        }
    }
    __syncthreads();
    {
        int hh = t >> 7, d = t & 127;
        float s = 0.f;
#pragma unroll
        for (int w = 0; w < 32; ++w) s += S[OFF_CTX0 + w * (NH * DCTX) + hh * DCTX + d];
        sc[hh * DCTX + d] = s;
    }
    __syncthreads();

    // scratch free again — start streaming pass-2 tile 0 under the small matvecs
    issue_tile(0, b, context, mask, S, t);

    // x[o] = (1/l_h) * sum_d c[h][d] * Wv[d,o]
    {
        int o = t >> 3, ks = t & 7, hh = o >> 4;
        float p = 0.f;
#pragma unroll
        for (int j = 0; j < 16; ++j) {
            int d = ks * 16 + j;
            p = fmaf(sc[hh * DCTX + d], Wv[d * HID + o], p);
        }
        p += __shfl_xor_sync(0xffffffffu, p, 4);
        p += __shfl_xor_sync(0xffffffffu, p, 2);
        p += __shfl_xor_sync(0xffffffffu, p, 1);
        if (ks == 0) sx[o] = p / sred[R_LRUN + hh];
    }
    __syncthreads();
    // xf = x @ Wfc
    {
        int o = t >> 3, ks = t & 7;
        float p = 0.f;
#pragma unroll
        for (int j = 0; j < 16; ++j) {
            int i = ks * 16 + j;
            p = fmaf(sx[i], Wfc[i * HID + o], p);
        }
        p += __shfl_xor_sync(0xffffffffu, p, 4);
        p += __shfl_xor_sync(0xffffffffu, p, 2);
        p += __shfl_xor_sync(0xffffffffu, p, 1);
        if (ks == 0) sxf[o] = p;
    }
    __syncthreads();
    // z[d] = (1/sqrt(HID)) * sum_o Wk[d,o] * xf[o]
    {
        int d = t >> 3, ks = t & 7;
        float p = 0.f;
#pragma unroll
        for (int j = 0; j < 16; ++j) {
            int o = ks * 16 + j;
            p = fmaf(Wk[d * HID + o], sxf[o], p);
        }
        p += __shfl_xor_sync(0xffffffffu, p, 4);
        p += __shfl_xor_sync(0xffffffffu, p, 2);
        p += __shfl_xor_sync(0xffffffffu, p, 1);
        if (ks == 0) sz[d] = 0.08838834764831845f * p;
    }
    issue_tile(1, b, context, mask, S, t);
    __syncthreads();

    // ---- pass 2: u[n] = 5*tanh(ctx[n].z), masked ----
    for (int tile = 0; tile < NTILES; ++tile) {
        const float* C = S + ((tile & 1) ? OFF_CTX1 : OFF_CTX0);
        const int*   M = (const int*)(S + OFF_MASK) + (tile & 1) * 128;

        if (tile + 2 < NTILES) { cp_wait<1>(); }
        else                   { cp_wait<0>(); }
        __syncthreads();

        int n = t >> 3, ks = t & 7;
        const float4* cr = (const float4*)(C + n * ROWP + ks * 16);
        const float4* zr = (const float4*)(sz + ks * 16);
        float p = 0.f;
#pragma unroll
        for (int i = 0; i < 4; ++i) {
            float4 a = cr[i], z = zr[i];
            p = fmaf(a.x, z.x, p); p = fmaf(a.y, z.y, p);
            p = fmaf(a.z, z.z, p); p = fmaf(a.w, z.w, p);
        }
        p += __shfl_xor_sync(0xffffffffu, p, 4);
        p += __shfl_xor_sync(0xffffffffu, p, 2);
        p += __shfl_xor_sync(0xffffffffu, p, 1);
        if (ks == 0) {
            int gn = tile * TN + n;
            if (gn < NCTX) su[gn] = (M[n] != 0) ? NEG_INF : 5.f * tanhf(p);
        }
        __syncthreads();

        if (tile + 2 < NTILES) issue_tile(tile + 2, b, context, mask, S, t);
    }
    __syncthreads();

    // ---- final masked softmax over u ----
    {
        float v = su[t];
        v = fmaxf(v, __shfl_xor_sync(0xffffffffu, v, 16));
        v = fmaxf(v, __shfl_xor_sync(0xffffffffu, v, 8));
        v = fmaxf(v, __shfl_xor_sync(0xffffffffu, v, 4));
        v = fmaxf(v, __shfl_xor_sync(0xffffffffu, v, 2));
        v = fmaxf(v, __shfl_xor_sync(0xffffffffu, v, 1));
        if (lane == 0) sred[R_WARP + wI] = v;
    }
    __syncthreads();
    if (t < 32) {
        float v = sred[R_WARP + t];
        v = fmaxf(v, __shfl_xor_sync(0xffffffffu, v, 16));
        v = fmaxf(v, __shfl_xor_sync(0xffffffffu, v, 8));
        v = fmaxf(v, __shfl_xor_sync(0xffffffffu, v, 4));
        v = fmaxf(v, __shfl_xor_sync(0xffffffffu, v, 2));
        v = fmaxf(v, __shfl_xor_sync(0xffffffffu, v, 1));
        if (t == 0) sred[R_UMAX] = v;
    }
    __syncthreads();

    float invT;
    {
        int iv = Tptr[0];
        float Tv = (iv >= 1 && iv <= 1000000) ? (float)iv : __int_as_float(iv);
        if (!(Tv > 0.f)) Tv = 1.f;
        invT = 1.f / Tv;
    }
    float umax = sred[R_UMAX];
    float e = __expf((su[t] - umax) * invT);  // -inf rows -> 0
    {
        float v = e;
        v += __shfl_xor_sync(0xffffffffu, v, 16);
        v += __shfl_xor_sync(0xffffffffu, v, 8);
        v += __shfl_xor_sync(0xffffffffu, v, 4);
        v += __shfl_xor_sync(0xffffffffu, v, 2);
        v += __shfl_xor_sync(0xffffffffu, v, 1);
        if (lane == 0) sred[R_WARP + wI] = v;
    }
    __syncthreads();
    if (t < 32) {
        float v = sred[R_WARP + t];
        v += __shfl_xor_sync(0xffffffffu, v, 16);
        v += __shfl_xor_sync(0xffffffffu, v, 8);
        v += __shfl_xor_sync(0xffffffffu, v, 4);
        v += __shfl_xor_sync(0xffffffffu, v, 2);
        v += __shfl_xor_sync(0xffffffffu, v, 1);
        if (t == 0) sred[R_USUM] = v;
    }
    __syncthreads();

    if (t < NCTX) out[(size_t)b * NCTX + t] = e / sred[R_USUM];
}

extern "C" void kernel_launch(void* const* d_in, const int* in_sizes, int n_in,
                              void* d_out, int out_size)
{
    const float* state_t = (const float*)d_in[0];
    const float* context = (const float*)d_in[1];
    const int*   mask    = (const int*)d_in[2];
    const float* Wq      = (const float*)d_in[3];
    const float* Wk_mha  = (const float*)d_in[4];
    const float* Wv      = (const float*)d_in[5];
    const float* Wfc     = (const float*)d_in[6];
    const float* Wk      = (const float*)d_in[7];
    const int*   Tptr    = (const int*)d_in[8];

    cudaFuncSetAttribute(pointer_attn_kernel,
                         cudaFuncAttributeMaxDynamicSharedMemorySize, SMEM_BYTES);
    pointer_attn_kernel<<<BATCH, TPB, SMEM_BYTES>>>(
        state_t, context, mask, Wq, Wk_mha, Wv, Wfc, Wk, Tptr, (float*)d_out);
}